// round 11
// baseline (speedup 1.0000x reference)
#include <cuda_runtime.h>
#include <cuda_bf16.h>
#include <math_constants.h>

// Soft cross entropy: mean_i [ sum_y target[i,y]*weight[y]*(lse_i - x[i,y]) ]
// N = 262144 rows, K = 512 cols, fp32. Output: single fp32 scalar.
//
// 2048 CTAs x 8 warps = 16384 warps, 16 rows/warp, software-pipelined double
// buffer: while row i computes (max/exp/shfl), the 8 LDG.E.128 for row i+1
// are in flight. unroll(2) keeps I-footprint L0-resident and lets ptxas
// register-rename the double buffer (no MOV copies).

#define K_DIM 512
#define WARPS_PER_BLOCK 8
#define THREADS (WARPS_PER_BLOCK * 32)
#define N_ROWS 262144
#define GRID_BLOCKS 2048
#define TOTAL_WARPS (GRID_BLOCKS * WARPS_PER_BLOCK)      // 16384
#define ROWS_PER_WARP (N_ROWS / TOTAL_WARPS)             // 16

__device__ float g_partials[TOTAL_WARPS];

// Per-row loss contribution from register-resident row. Warp-collective.
__device__ __forceinline__ float row_loss(const float4 v[4], const float4 tv[4],
                                          const float4* __restrict__ wr, int lane)
{
    // row max
    float m = -CUDART_INF_F;
#pragma unroll
    for (int j = 0; j < 4; j++)
        m = fmaxf(m, fmaxf(fmaxf(v[j].x, v[j].y), fmaxf(v[j].z, v[j].w)));
#pragma unroll
    for (int o = 16; o > 0; o >>= 1)
        m = fmaxf(m, __shfl_xor_sync(0xFFFFFFFFu, m, o));

    // sum exp(x - m)
    float s = 0.f;
#pragma unroll
    for (int j = 0; j < 4; j++) {
        s += __expf(v[j].x - m);
        s += __expf(v[j].y - m);
        s += __expf(v[j].z - m);
        s += __expf(v[j].w - m);
    }

    // t*w sums (independent of the exp chain -> dual-issues against MUFU)
    float s1 = 0.f, s2 = 0.f;
#pragma unroll
    for (int j = 0; j < 4; j++) {
        float4 wv = wr[j * 32 + lane];
        float a0 = tv[j].x * wv.x;
        float a1 = tv[j].y * wv.y;
        float a2 = tv[j].z * wv.z;
        float a3 = tv[j].w * wv.w;
        s1 += a0 + a1 + a2 + a3;
        s2 = fmaf(a0, v[j].x, s2);
        s2 = fmaf(a1, v[j].y, s2);
        s2 = fmaf(a2, v[j].z, s2);
        s2 = fmaf(a3, v[j].w, s2);
    }

    // fused warp reduction of (s, s1, s2)
#pragma unroll
    for (int o = 16; o > 0; o >>= 1) {
        s  += __shfl_xor_sync(0xFFFFFFFFu, s,  o);
        s1 += __shfl_xor_sync(0xFFFFFFFFu, s1, o);
        s2 += __shfl_xor_sync(0xFFFFFFFFu, s2, o);
    }

    const float lse = m + __logf(s);
    return fmaf(s1, lse, -s2);
}

__global__ __launch_bounds__(THREADS, 2) void soft_ce_main(
    const float* __restrict__ x,
    const float* __restrict__ t,
    const float* __restrict__ w)
{
    __shared__ float sw[K_DIM];

    const int tid  = threadIdx.x;
    const int lane = tid & 31;
    const int warp = tid >> 5;
    const int gw   = blockIdx.x * WARPS_PER_BLOCK + warp;   // global warp id

    if (tid < K_DIM / 4) {
        reinterpret_cast<float4*>(sw)[tid] = reinterpret_cast<const float4*>(w)[tid];
    }
    __syncthreads();
    const float4* wr = reinterpret_cast<const float4*>(sw);

    float acc = 0.f;

    // Prologue: loads for row 0 in flight.
    {
        const float4* xr = reinterpret_cast<const float4*>(x + (long long)gw * K_DIM);
        const float4* tr = reinterpret_cast<const float4*>(t + (long long)gw * K_DIM);
        float4 va[4], ta[4];
#pragma unroll
        for (int j = 0; j < 4; j++) va[j] = xr[j * 32 + lane];
#pragma unroll
        for (int j = 0; j < 4; j++) ta[j] = tr[j * 32 + lane];

#pragma unroll 2
        for (int it = 0; it < ROWS_PER_WARP; it++) {
            float4 vb[4], tb[4];
            if (it + 1 < ROWS_PER_WARP) {
                long long nrow = (long long)gw + (long long)(it + 1) * TOTAL_WARPS;
                const float4* xn = reinterpret_cast<const float4*>(x + nrow * K_DIM);
                const float4* tn = reinterpret_cast<const float4*>(t + nrow * K_DIM);
#pragma unroll
                for (int j = 0; j < 4; j++) vb[j] = xn[j * 32 + lane];
#pragma unroll
                for (int j = 0; j < 4; j++) tb[j] = tn[j * 32 + lane];
            }

            acc += row_loss(va, ta, wr, lane);

            if (it + 1 < ROWS_PER_WARP) {
#pragma unroll
                for (int j = 0; j < 4; j++) { va[j] = vb[j]; ta[j] = tb[j]; }
            }
        }
    }

    if (lane == 0) g_partials[gw] = acc;
}

// Single-block reduction of 16384 partials -> mean (double accumulate).
__global__ __launch_bounds__(1024) void soft_ce_reduce(float* out)
{
    __shared__ double sred[32];
    const int tid = threadIdx.x;
    double acc = 0.0;
    for (int i = tid; i < TOTAL_WARPS; i += 1024) acc += (double)g_partials[i];
#pragma unroll
    for (int o = 16; o > 0; o >>= 1)
        acc += __shfl_xor_sync(0xFFFFFFFFu, acc, o);
    if ((tid & 31) == 0) sred[tid >> 5] = acc;
    __syncthreads();
    if (tid < 32) {
        double a = sred[tid];
#pragma unroll
        for (int o = 16; o > 0; o >>= 1)
            a += __shfl_xor_sync(0xFFFFFFFFu, a, o);
        if (tid == 0) out[0] = (float)(a / (double)N_ROWS);
    }
}

extern "C" void kernel_launch(void* const* d_in, const int* in_sizes, int n_in,
                              void* d_out, int out_size)
{
    const float* x = (const float*)d_in[0];
    const float* t = (const float*)d_in[1];
    const float* w = (const float*)d_in[2];
    float* out = (float*)d_out;

    soft_ce_main<<<GRID_BLOCKS, THREADS>>>(x, t, w);
    soft_ce_reduce<<<1, 1024>>>(out);
}

// round 14
// speedup vs baseline: 1.0369x; 1.0369x over previous
#include <cuda_runtime.h>
#include <cuda_bf16.h>
#include <math_constants.h>

// Soft cross entropy: mean_i [ sum_y target[i,y]*weight[y]*(lse_i - x[i,y]) ]
// N = 262144 rows, K = 512 cols, fp32. Output: single fp32 scalar.
//
// Single fused kernel. 2048 CTAs x 8 warps, 16 rows/warp, software-pipelined
// double buffer (8 LDG.E.128 in flight while previous row computes).
// Epilogue: per-CTA block reduce -> g_partials[2048] -> threadfence-reduction
// "last CTA" pattern sums the L2-hot partials in double (fixed order,
// deterministic) and resets the ticket counter for graph replay safety.

#define K_DIM 512
#define WARPS_PER_BLOCK 8
#define THREADS (WARPS_PER_BLOCK * 32)
#define N_ROWS 262144
#define GRID_BLOCKS 2048
#define TOTAL_WARPS (GRID_BLOCKS * WARPS_PER_BLOCK)      // 16384
#define ROWS_PER_WARP (N_ROWS / TOTAL_WARPS)             // 16

__device__ float g_partials[GRID_BLOCKS];
__device__ unsigned int g_counter = 0;

// Per-row loss contribution from register-resident row. Warp-collective.
__device__ __forceinline__ float row_loss(const float4 v[4], const float4 tv[4],
                                          const float4* __restrict__ wr, int lane)
{
    // row max
    float m = -CUDART_INF_F;
#pragma unroll
    for (int j = 0; j < 4; j++)
        m = fmaxf(m, fmaxf(fmaxf(v[j].x, v[j].y), fmaxf(v[j].z, v[j].w)));
#pragma unroll
    for (int o = 16; o > 0; o >>= 1)
        m = fmaxf(m, __shfl_xor_sync(0xFFFFFFFFu, m, o));

    // sum exp(x - m)
    float s = 0.f;
#pragma unroll
    for (int j = 0; j < 4; j++) {
        s += __expf(v[j].x - m);
        s += __expf(v[j].y - m);
        s += __expf(v[j].z - m);
        s += __expf(v[j].w - m);
    }

    // t*w sums (independent of the exp chain -> dual-issues against MUFU)
    float s1 = 0.f, s2 = 0.f;
#pragma unroll
    for (int j = 0; j < 4; j++) {
        float4 wv = wr[j * 32 + lane];
        float a0 = tv[j].x * wv.x;
        float a1 = tv[j].y * wv.y;
        float a2 = tv[j].z * wv.z;
        float a3 = tv[j].w * wv.w;
        s1 += a0 + a1 + a2 + a3;
        s2 = fmaf(a0, v[j].x, s2);
        s2 = fmaf(a1, v[j].y, s2);
        s2 = fmaf(a2, v[j].z, s2);
        s2 = fmaf(a3, v[j].w, s2);
    }

    // fused warp reduction of (s, s1, s2)
#pragma unroll
    for (int o = 16; o > 0; o >>= 1) {
        s  += __shfl_xor_sync(0xFFFFFFFFu, s,  o);
        s1 += __shfl_xor_sync(0xFFFFFFFFu, s1, o);
        s2 += __shfl_xor_sync(0xFFFFFFFFu, s2, o);
    }

    const float lse = m + __logf(s);
    return fmaf(s1, lse, -s2);
}

__global__ __launch_bounds__(THREADS, 2) void soft_ce_fused(
    const float* __restrict__ x,
    const float* __restrict__ t,
    const float* __restrict__ w,
    float* __restrict__ out)
{
    __shared__ float sw[K_DIM];
    __shared__ float warp_out[WARPS_PER_BLOCK];
    __shared__ bool is_last;
    __shared__ double dred[WARPS_PER_BLOCK];

    const int tid  = threadIdx.x;
    const int lane = tid & 31;
    const int warp = tid >> 5;
    const int gw   = blockIdx.x * WARPS_PER_BLOCK + warp;   // global warp id

    if (tid < K_DIM / 4) {
        reinterpret_cast<float4*>(sw)[tid] = reinterpret_cast<const float4*>(w)[tid];
    }
    __syncthreads();
    const float4* wr = reinterpret_cast<const float4*>(sw);

    float acc = 0.f;

    // Mainloop: identical to the validated 170us kernel (main part ~154us).
    {
        const float4* xr = reinterpret_cast<const float4*>(x + (long long)gw * K_DIM);
        const float4* tr = reinterpret_cast<const float4*>(t + (long long)gw * K_DIM);
        float4 va[4], ta[4];
#pragma unroll
        for (int j = 0; j < 4; j++) va[j] = xr[j * 32 + lane];
#pragma unroll
        for (int j = 0; j < 4; j++) ta[j] = tr[j * 32 + lane];

#pragma unroll 2
        for (int it = 0; it < ROWS_PER_WARP; it++) {
            float4 vb[4], tb[4];
            if (it + 1 < ROWS_PER_WARP) {
                long long nrow = (long long)gw + (long long)(it + 1) * TOTAL_WARPS;
                const float4* xn = reinterpret_cast<const float4*>(x + nrow * K_DIM);
                const float4* tn = reinterpret_cast<const float4*>(t + nrow * K_DIM);
#pragma unroll
                for (int j = 0; j < 4; j++) vb[j] = xn[j * 32 + lane];
#pragma unroll
                for (int j = 0; j < 4; j++) tb[j] = tn[j * 32 + lane];
            }

            acc += row_loss(va, ta, wr, lane);

            if (it + 1 < ROWS_PER_WARP) {
#pragma unroll
                for (int j = 0; j < 4; j++) { va[j] = vb[j]; ta[j] = tb[j]; }
            }
        }
    }

    // ---- Per-CTA block reduce -> one partial per CTA ----
    if (lane == 0) warp_out[warp] = acc;
    __syncthreads();

    if (tid == 0) {
        float bsum = 0.f;
#pragma unroll
        for (int i = 0; i < WARPS_PER_BLOCK; i++) bsum += warp_out[i];
        g_partials[blockIdx.x] = bsum;
        __threadfence();
        unsigned int old = atomicAdd(&g_counter, 1u);
        is_last = (old == GRID_BLOCKS - 1);
    }
    __syncthreads();

    // ---- Last CTA: deterministic fixed-order double reduce of 2048 partials ----
    if (is_last) {
        __threadfence();  // make all g_partials writes visible

        double a = 0.0;
        for (int i = tid; i < GRID_BLOCKS; i += THREADS)
            a += (double)g_partials[i];
#pragma unroll
        for (int o = 16; o > 0; o >>= 1)
            a += __shfl_xor_sync(0xFFFFFFFFu, a, o);
        if (lane == 0) dred[warp] = a;
        __syncthreads();
        if (tid == 0) {
            double tot = 0.0;
#pragma unroll
            for (int i = 0; i < WARPS_PER_BLOCK; i++) tot += dred[i];
            out[0] = (float)(tot / (double)N_ROWS);
            g_counter = 0;  // reset for next graph replay
        }
    }
}

extern "C" void kernel_launch(void* const* d_in, const int* in_sizes, int n_in,
                              void* d_out, int out_size)
{
    const float* x = (const float*)d_in[0];
    const float* t = (const float*)d_in[1];
    const float* w = (const float*)d_in[2];
    float* out = (float*)d_out;

    soft_ce_fused<<<GRID_BLOCKS, THREADS>>>(x, t, w, out);
}